// round 7
// baseline (speedup 1.0000x reference)
#include <cuda_runtime.h>
#include <math_constants.h>

// out[c] = dequant(quant(x[c])) with channel c's quant group = inv[c]>>7.
// Block = 4 rows interleaved in smem (s4[c] = {r0..r3}[c]): one LDS.128
// serves 4 rows. A prologue kernel reorders each group's 128 perm indices
// (order is free for min/max) so gather LDS.128 phases are ~conflict-free.
// Params: exact inv_scale in an 8x-replicated float4 table; 4-bit bases
// packed per group in a 32x-replicated uint table; scale = rcp(inv) in pass B.

#define ROW_C 4096
#define NT    1024
#define RPT   4
#define Q_MAX 15.0f
#define EPS   1e-5f

__device__ int g_sperm[ROW_C];

// Reorder each group's 128 indices so that each 8-position cell (one LDS.128
// phase) has ~distinct (idx&7) bank-quads. Pure function of perm.
__global__ void sort_perm_kernel(const int* __restrict__ perm)
{
    __shared__ int S[32][129];                 // 129: de-conflict across threads
    const int w = threadIdx.x;                 // one group per thread (32)
    int cnt[8], off[8], ptr[8], end_[8];
    #pragma unroll
    for (int r = 0; r < 8; ++r) cnt[r] = 0;
    for (int i = 0; i < 128; ++i) cnt[perm[w * 128 + i] & 7]++;
    int acc = 0;
    #pragma unroll
    for (int r = 0; r < 8; ++r) { off[r] = acc; acc += cnt[r]; }
    #pragma unroll
    for (int r = 0; r < 8; ++r) { ptr[r] = off[r]; end_[r] = off[r] + cnt[r]; }
    {   // counting-sort placement by residue
        int p2[8];
        #pragma unroll
        for (int r = 0; r < 8; ++r) p2[r] = off[r];
        for (int i = 0; i < 128; ++i) {
            const int v = perm[w * 128 + i];
            S[w][p2[v & 7]++] = v;
        }
    }
    int pos = 0;                               // emit: residue round-robin/cell
    for (int c = 0; c < 16; ++c) {
        for (int s = 0; s < 8; ++s) {
            int r = (s + c) & 7;
            if (ptr[r] >= end_[r]) {           // fallback: largest remaining bin
                int best = 0, bb = -1;
                #pragma unroll
                for (int j = 0; j < 8; ++j) {
                    const int rem = end_[j] - ptr[j];
                    if (rem > bb) { bb = rem; best = j; }
                }
                r = best;
            }
            g_sperm[w * 128 + pos++] = S[w][ptr[r]++];
        }
    }
}

extern __shared__ float4 smem_dyn[];

__global__ __launch_bounds__(NT, 2)
void tpq_kernel(const float* __restrict__ x,
                const int*   __restrict__ inv,
                float*       __restrict__ out)
{
    float4*   s4      = smem_dyn;                    // [4096] float4 = 64 KB
    float4*   tab_inv = s4 + ROW_C;                  // [32*8]  float4 =  4 KB
    unsigned* tab_b   = (unsigned*)(tab_inv + 32 * 8); // [32*32] uint  =  4 KB

    const int t    = threadIdx.x;
    const int warp = t >> 5;
    const int lane = t & 31;
    const int m8   = lane & 7;
    const size_t rowbase = (size_t)blockIdx.x * (RPT * ROW_C);

    // ---- stage 4 rows interleaved; coalesced streaming loads ----
    #pragma unroll
    for (int k = 0; k < 4; ++k) {
        const size_t c = rowbase + t + 1024 * k;
        s4[t + 1024 * k] = make_float4(__ldcs(&x[c]),
                                       __ldcs(&x[c + ROW_C]),
                                       __ldcs(&x[c + 2 * ROW_C]),
                                       __ldcs(&x[c + 3 * ROW_C]));
    }

    int pp[4];                                       // bank-sorted gather idx
    #pragma unroll
    for (int i = 0; i < 4; ++i)
        pp[i] = g_sperm[warp * 128 + i * 32 + lane];
    __syncthreads();

    // ---- pass A: warp w reduces permuted group w for all 4 rows ----
    float mn[RPT], mx[RPT];
    #pragma unroll
    for (int r = 0; r < RPT; ++r) { mn[r] = CUDART_INF_F; mx[r] = -CUDART_INF_F; }

    #pragma unroll
    for (int i = 0; i < 4; ++i) {
        const float4 w4 = s4[pp[i]];                 // ~conflict-free gather
        mn[0] = fminf(mn[0], w4.x);  mx[0] = fmaxf(mx[0], w4.x);
        mn[1] = fminf(mn[1], w4.y);  mx[1] = fmaxf(mx[1], w4.y);
        mn[2] = fminf(mn[2], w4.z);  mx[2] = fmaxf(mx[2], w4.z);
        mn[3] = fminf(mn[3], w4.w);  mx[3] = fmaxf(mx[3], w4.w);
    }
    #pragma unroll
    for (int off = 16; off; off >>= 1) {
        #pragma unroll
        for (int r = 0; r < RPT; ++r) {
            mn[r] = fminf(mn[r], __shfl_xor_sync(0xffffffffu, mn[r], off));
            mx[r] = fmaxf(mx[r], __shfl_xor_sync(0xffffffffu, mx[r], off));
        }
    }

    // params: exact inv_scale table (8x repl) + packed 4-bit bases (32x repl)
    {
        float4 iv;
        float* ivp = (float*)&iv;
        unsigned bu = 0;
        #pragma unroll
        for (int r = 0; r < RPT; ++r) {
            const float scale = fmaxf(mx[r] - mn[r], EPS) / Q_MAX;
            const float inv_s = 1.0f / scale;
            const float base  = fminf(fmaxf(rintf(-mn[r] * inv_s), 0.0f), Q_MAX);
            ivp[r] = inv_s;
            bu |= ((unsigned)base) << (4 * r);
        }
        if (lane < 8) tab_inv[warp * 8 + lane] = iv;
        tab_b[warp * 32 + lane] = bu;                // conflict-free (bank=lane)
    }

    int g[4];
    #pragma unroll
    for (int k = 0; k < 4; ++k)
        g[k] = __ldg(&inv[t + 1024 * k]) >> 7;
    __syncthreads();

    // ---- pass B: reread staged values, quantize, coalesced stores ----
    #pragma unroll
    for (int k = 0; k < 4; ++k) {
        const float4   d  = s4[t + 1024 * k];        // 4 rows' values
        const float4   iv = tab_inv[g[k] * 8 + m8];  // conflict-free
        const unsigned bu = tab_b [g[k] * 32 + lane];// conflict-free
        const float* dp  = (const float*)&d;
        const float* ivp = (const float*)&iv;
        const size_t c = rowbase + t + 1024 * k;
        #pragma unroll
        for (int r = 0; r < RPT; ++r) {
            float sc;                                // scale = rcp(inv_scale):
            asm("rcp.approx.f32 %0, %1;" : "=f"(sc) : "f"(ivp[r]));
            const float b = (float)((bu >> (4 * r)) & 15u);
            float q = rintf(dp[r] * ivp[r]);
            q = fminf(fmaxf(q, -b), Q_MAX - b);      // == clip(q+b,0,15)-b
            __stcg(&out[c + r * ROW_C], q * sc);
        }
    }
}

extern "C" void kernel_launch(void* const* d_in, const int* in_sizes, int n_in,
                              void* d_out, int out_size)
{
    const float* x    = (const float*)d_in[0];
    const int*   perm = (const int*)d_in[1];
    const int*   inv  = (const int*)d_in[2];
    float*       out  = (float*)d_out;

    sort_perm_kernel<<<1, 32>>>(perm);

    const int smem_bytes = ROW_C * sizeof(float4)
                         + 32 * 8 * sizeof(float4)
                         + 32 * 32 * sizeof(unsigned);
    cudaFuncSetAttribute(tpq_kernel,
                         cudaFuncAttributeMaxDynamicSharedMemorySize, smem_bytes);

    const int rows = in_sizes[0] / ROW_C;            // 16384
    tpq_kernel<<<rows / RPT, NT, smem_bytes>>>(x, inv, out);
}

// round 8
// speedup vs baseline: 1.2491x; 1.2491x over previous
#include <cuda_runtime.h>
#include <math_constants.h>

// out[c] = dequant(quant(x[c])) with channel c's quant group = inv[c]>>7.
// Block = 4 rows interleaved in smem (s4[c] = {r0..r3}[c]): one LDS.128
// serves 4 rows. A (now warp-parallel) prologue reorders each group's 128
// perm indices (order is free for min/max) so gather LDS.128 phases are
// ~conflict-free. Params: exact inv_scale in an 8x-replicated float4 table;
// 4-bit bases packed per group (32x repl); scale = rcp(inv_scale) in pass B.

#define ROW_C 4096
#define NT    1024
#define RPT   4
#define Q_MAX 15.0f
#define EPS   1e-5f

__device__ int g_sperm[ROW_C];

// One warp per group. Counting-sort the group's 128 indices by (idx&7)
// (rank via smem atomics; within-residue order is irrelevant), then lane 0
// emits round-robin over residues (greedy fallback) so each 8-wide LDS.128
// phase sees ~distinct bank-quads. Output order is nondeterministic only
// within a residue bin, which min/max reduction cannot observe.
__global__ void sort_perm_kernel(const int* __restrict__ perm)
{
    __shared__ int sorted[32][128];
    __shared__ int emit  [32][128];
    __shared__ int cnt[32][8], rk[32][8], off[32][8];

    const int w    = threadIdx.x >> 5;
    const int lane = threadIdx.x & 31;

    if (lane < 8) { cnt[w][lane] = 0; rk[w][lane] = 0; }
    __syncwarp();

    int v[4];
    #pragma unroll
    for (int i = 0; i < 4; ++i) {
        v[i] = perm[w * 128 + i * 32 + lane];          // coalesced
        atomicAdd(&cnt[w][v[i] & 7], 1);
    }
    __syncwarp();

    if (lane == 0) {
        int acc = 0;
        #pragma unroll
        for (int r = 0; r < 8; ++r) { off[w][r] = acc; acc += cnt[w][r]; }
    }
    __syncwarp();

    #pragma unroll
    for (int i = 0; i < 4; ++i) {
        const int r = v[i] & 7;
        sorted[w][off[w][r] + atomicAdd(&rk[w][r], 1)] = v[i];
    }
    __syncwarp();

    if (lane == 0) {
        int ptr[8], end_[8];
        #pragma unroll
        for (int r = 0; r < 8; ++r) {
            ptr[r]  = off[w][r];
            end_[r] = off[w][r] + cnt[w][r];
        }
        int pos = 0;
        for (int c = 0; c < 16; ++c) {
            #pragma unroll
            for (int s = 0; s < 8; ++s) {
                int r = (s + c) & 7;
                if (ptr[r] >= end_[r]) {               // largest remaining bin
                    int best = 0, bb = -1;
                    #pragma unroll
                    for (int j = 0; j < 8; ++j) {
                        const int rem = end_[j] - ptr[j];
                        if (rem > bb) { bb = rem; best = j; }
                    }
                    r = best;
                }
                emit[w][pos++] = sorted[w][ptr[r]++];
            }
        }
    }
    __syncwarp();

    #pragma unroll
    for (int i = 0; i < 4; ++i)
        g_sperm[w * 128 + i * 32 + lane] = emit[w][i * 32 + lane];  // coalesced
}

extern __shared__ float4 smem_dyn[];

__global__ __launch_bounds__(NT, 2)
void tpq_kernel(const float* __restrict__ x,
                const int*   __restrict__ inv,
                float*       __restrict__ out)
{
    float4*   s4      = smem_dyn;                      // [4096] float4 = 64 KB
    float4*   tab_inv = s4 + ROW_C;                    // [32*8]  float4 =  4 KB
    unsigned* tab_b   = (unsigned*)(tab_inv + 32 * 8); // [32*32] uint  =  4 KB

    const int t    = threadIdx.x;
    const int warp = t >> 5;
    const int lane = t & 31;
    const int m8   = lane & 7;
    const size_t rowbase = (size_t)blockIdx.x * (RPT * ROW_C);

    // ---- stage 4 rows interleaved; coalesced streaming loads ----
    #pragma unroll
    for (int k = 0; k < 4; ++k) {
        const size_t c = rowbase + t + 1024 * k;
        s4[t + 1024 * k] = make_float4(__ldcs(&x[c]),
                                       __ldcs(&x[c + ROW_C]),
                                       __ldcs(&x[c + 2 * ROW_C]),
                                       __ldcs(&x[c + 3 * ROW_C]));
    }

    int pp[4];                                         // bank-sorted gather idx
    #pragma unroll
    for (int i = 0; i < 4; ++i)
        pp[i] = g_sperm[warp * 128 + i * 32 + lane];
    __syncthreads();

    // ---- pass A: warp w reduces permuted group w for all 4 rows ----
    float mn[RPT], mx[RPT];
    #pragma unroll
    for (int r = 0; r < RPT; ++r) { mn[r] = CUDART_INF_F; mx[r] = -CUDART_INF_F; }

    #pragma unroll
    for (int i = 0; i < 4; ++i) {
        const float4 w4 = s4[pp[i]];                   // ~conflict-free gather
        mn[0] = fminf(mn[0], w4.x);  mx[0] = fmaxf(mx[0], w4.x);
        mn[1] = fminf(mn[1], w4.y);  mx[1] = fmaxf(mx[1], w4.y);
        mn[2] = fminf(mn[2], w4.z);  mx[2] = fmaxf(mx[2], w4.z);
        mn[3] = fminf(mn[3], w4.w);  mx[3] = fmaxf(mx[3], w4.w);
    }
    #pragma unroll
    for (int off = 16; off; off >>= 1) {
        #pragma unroll
        for (int r = 0; r < RPT; ++r) {
            mn[r] = fminf(mn[r], __shfl_xor_sync(0xffffffffu, mn[r], off));
            mx[r] = fmaxf(mx[r], __shfl_xor_sync(0xffffffffu, mx[r], off));
        }
    }

    // params: exact inv_scale table (8x repl) + packed 4-bit bases (32x repl)
    {
        float4 iv;
        float* ivp = (float*)&iv;
        unsigned bu = 0;
        #pragma unroll
        for (int r = 0; r < RPT; ++r) {
            const float scale = fmaxf(mx[r] - mn[r], EPS) / Q_MAX;
            const float inv_s = 1.0f / scale;
            const float base  = fminf(fmaxf(rintf(-mn[r] * inv_s), 0.0f), Q_MAX);
            ivp[r] = inv_s;
            bu |= ((unsigned)base) << (4 * r);
        }
        if (lane < 8) tab_inv[warp * 8 + lane] = iv;
        tab_b[warp * 32 + lane] = bu;                  // conflict-free
    }

    int g[4];
    #pragma unroll
    for (int k = 0; k < 4; ++k)
        g[k] = __ldg(&inv[t + 1024 * k]) >> 7;
    __syncthreads();

    // ---- pass B: reread staged values, quantize, coalesced stores ----
    #pragma unroll
    for (int k = 0; k < 4; ++k) {
        const float4   d  = s4[t + 1024 * k];          // 4 rows' values
        const float4   iv = tab_inv[g[k] * 8 + m8];    // conflict-free
        const unsigned bu = tab_b [g[k] * 32 + lane];  // conflict-free
        const float* dp  = (const float*)&d;
        const float* ivp = (const float*)&iv;
        const size_t c = rowbase + t + 1024 * k;
        #pragma unroll
        for (int r = 0; r < RPT; ++r) {
            float sc;                                  // scale = rcp(inv_scale)
            asm("rcp.approx.f32 %0, %1;" : "=f"(sc) : "f"(ivp[r]));
            const float b = (float)((bu >> (4 * r)) & 15u);
            float q = rintf(dp[r] * ivp[r]);
            q = fminf(fmaxf(q, -b), Q_MAX - b);        // == clip(q+b,0,15)-b
            __stcg(&out[c + r * ROW_C], q * sc);
        }
    }
}

extern "C" void kernel_launch(void* const* d_in, const int* in_sizes, int n_in,
                              void* d_out, int out_size)
{
    const float* x    = (const float*)d_in[0];
    const int*   perm = (const int*)d_in[1];
    const int*   inv  = (const int*)d_in[2];
    float*       out  = (float*)d_out;

    sort_perm_kernel<<<1, NT>>>(perm);

    const int smem_bytes = ROW_C * sizeof(float4)
                         + 32 * 8 * sizeof(float4)
                         + 32 * 32 * sizeof(unsigned);
    cudaFuncSetAttribute(tpq_kernel,
                         cudaFuncAttributeMaxDynamicSharedMemorySize, smem_bytes);

    const int rows = in_sizes[0] / ROW_C;              // 16384
    tpq_kernel<<<rows / RPT, NT, smem_bytes>>>(x, inv, out);
}

// round 9
// speedup vs baseline: 1.3953x; 1.1171x over previous
#include <cuda_runtime.h>
#include <math_constants.h>

// out[c] = dequant(quant(x[c])) with channel c's quant group = inv[c]>>7.
// Block = 4 rows interleaved in smem (s4[c] = {r0..r3}[c]): one LDS.128
// serves 4 rows. A fully warp-parallel prologue reorders each group's 128
// perm indices (order is free for min/max) so gather LDS.128 phases are
// ~conflict-free: element (residue r, rank k<16) -> pos k*8+((r-k)&7);
// overflow ranks fill the exact complement holes. Params: exact inv_scale
// (8x-repl float4) + packed 4-bit bases (32x repl); scale = rcp(inv_scale).

#define ROW_C 4096
#define NT    1024
#define RPT   4
#define Q_MAX 15.0f
#define EPS   1e-5f

__device__ int g_sperm[ROW_C];

// One warp per group; no serial emission. Positions are closed-form for
// rank<16; holes (complement) absorb overflow via atomic compaction.
__global__ void sort_perm_kernel(const int* __restrict__ perm)
{
    __shared__ int emit [32][128];
    __shared__ int holes[32][128];
    __shared__ int cnt[32][8], rk[32][8];
    __shared__ int nhole[32], nov[32];

    const int w    = threadIdx.x >> 5;
    const int lane = threadIdx.x & 31;

    if (lane < 8) { cnt[w][lane] = 0; rk[w][lane] = 0; }
    if (lane == 0) { nhole[w] = 0; nov[w] = 0; }
    __syncwarp();

    int v[4];
    #pragma unroll
    for (int i = 0; i < 4; ++i) {
        v[i] = perm[w * 128 + i * 32 + lane];            // coalesced
        atomicAdd(&cnt[w][v[i] & 7], 1);
    }
    __syncwarp();

    // holes: p=c*8+s is unfilled iff bin (s+c)&7 has cnt <= c
    #pragma unroll
    for (int i = 0; i < 4; ++i) {
        const int p = i * 32 + lane;
        const int c = p >> 3, s = p & 7;
        if (cnt[w][(s + c) & 7] <= c)
            holes[w][atomicAdd(&nhole[w], 1)] = p;
    }
    __syncwarp();

    #pragma unroll
    for (int i = 0; i < 4; ++i) {
        const int r = v[i] & 7;
        const int k = atomicAdd(&rk[w][r], 1);
        const int pos = (k < 16) ? (k * 8 + ((r - k) & 7))
                                 : holes[w][atomicAdd(&nov[w], 1)];
        emit[w][pos] = v[i];
    }
    __syncwarp();

    #pragma unroll
    for (int i = 0; i < 4; ++i)
        g_sperm[w * 128 + i * 32 + lane] = emit[w][i * 32 + lane];
}

extern __shared__ float4 smem_dyn[];

__global__ __launch_bounds__(NT, 2)
void tpq_kernel(const float* __restrict__ x,
                const int*   __restrict__ inv,
                float*       __restrict__ out)
{
    float4*   s4      = smem_dyn;                      // [4096] float4 = 64 KB
    float4*   tab_inv = s4 + ROW_C;                    // [32*8]  float4 =  4 KB
    unsigned* tab_b   = (unsigned*)(tab_inv + 32 * 8); // [32*32] uint  =  4 KB

    const int t    = threadIdx.x;
    const int warp = t >> 5;
    const int lane = t & 31;
    const int m8   = lane & 7;
    const size_t rowbase = (size_t)blockIdx.x * (RPT * ROW_C);

    // ---- stage 4 rows interleaved; coalesced streaming loads ----
    #pragma unroll
    for (int k = 0; k < 4; ++k) {
        const size_t c = rowbase + t + 1024 * k;
        s4[t + 1024 * k] = make_float4(__ldcs(&x[c]),
                                       __ldcs(&x[c + ROW_C]),
                                       __ldcs(&x[c + 2 * ROW_C]),
                                       __ldcs(&x[c + 3 * ROW_C]));
    }

    int pp[4];                                         // bank-sorted gather idx
    #pragma unroll
    for (int i = 0; i < 4; ++i)
        pp[i] = g_sperm[warp * 128 + i * 32 + lane];
    __syncthreads();

    // ---- pass A: warp w reduces permuted group w for all 4 rows ----
    float mn[RPT], mx[RPT];
    #pragma unroll
    for (int r = 0; r < RPT; ++r) { mn[r] = CUDART_INF_F; mx[r] = -CUDART_INF_F; }

    #pragma unroll
    for (int i = 0; i < 4; ++i) {
        const float4 w4 = s4[pp[i]];                   // ~conflict-free gather
        mn[0] = fminf(mn[0], w4.x);  mx[0] = fmaxf(mx[0], w4.x);
        mn[1] = fminf(mn[1], w4.y);  mx[1] = fmaxf(mx[1], w4.y);
        mn[2] = fminf(mn[2], w4.z);  mx[2] = fmaxf(mx[2], w4.z);
        mn[3] = fminf(mn[3], w4.w);  mx[3] = fmaxf(mx[3], w4.w);
    }
    #pragma unroll
    for (int off = 16; off; off >>= 1) {
        #pragma unroll
        for (int r = 0; r < RPT; ++r) {
            mn[r] = fminf(mn[r], __shfl_xor_sync(0xffffffffu, mn[r], off));
            mx[r] = fmaxf(mx[r], __shfl_xor_sync(0xffffffffu, mx[r], off));
        }
    }

    // params: exact inv_scale table (8x repl) + packed 4-bit bases (32x repl)
    {
        float4 iv;
        float* ivp = (float*)&iv;
        unsigned bu = 0;
        #pragma unroll
        for (int r = 0; r < RPT; ++r) {
            const float scale = fmaxf(mx[r] - mn[r], EPS) / Q_MAX;
            const float inv_s = 1.0f / scale;
            const float base  = fminf(fmaxf(rintf(-mn[r] * inv_s), 0.0f), Q_MAX);
            ivp[r] = inv_s;
            bu |= ((unsigned)base) << (4 * r);
        }
        if (lane < 8) tab_inv[warp * 8 + lane] = iv;
        tab_b[warp * 32 + lane] = bu;                  // conflict-free
    }

    int g[4];
    #pragma unroll
    for (int k = 0; k < 4; ++k)
        g[k] = __ldg(&inv[t + 1024 * k]) >> 7;
    __syncthreads();

    // ---- pass B: reread staged values, quantize, coalesced stores ----
    #pragma unroll
    for (int k = 0; k < 4; ++k) {
        const float4   d  = s4[t + 1024 * k];          // 4 rows' values
        const float4   iv = tab_inv[g[k] * 8 + m8];    // conflict-free
        const unsigned bu = tab_b [g[k] * 32 + lane];  // conflict-free
        const float* dp  = (const float*)&d;
        const float* ivp = (const float*)&iv;
        const size_t c = rowbase + t + 1024 * k;
        #pragma unroll
        for (int r = 0; r < RPT; ++r) {
            float sc;                                  // scale = rcp(inv_scale)
            asm("rcp.approx.f32 %0, %1;" : "=f"(sc) : "f"(ivp[r]));
            const float b = (float)((bu >> (4 * r)) & 15u);
            float q = rintf(dp[r] * ivp[r]);
            q = fminf(fmaxf(q, -b), Q_MAX - b);        // == clip(q+b,0,15)-b
            __stcg(&out[c + r * ROW_C], q * sc);
        }
    }
}

extern "C" void kernel_launch(void* const* d_in, const int* in_sizes, int n_in,
                              void* d_out, int out_size)
{
    const float* x    = (const float*)d_in[0];
    const int*   perm = (const int*)d_in[1];
    const int*   inv  = (const int*)d_in[2];
    float*       out  = (float*)d_out;

    sort_perm_kernel<<<1, NT>>>(perm);

    const int smem_bytes = ROW_C * sizeof(float4)
                         + 32 * 8 * sizeof(float4)
                         + 32 * 32 * sizeof(unsigned);
    cudaFuncSetAttribute(tpq_kernel,
                         cudaFuncAttributeMaxDynamicSharedMemorySize, smem_bytes);

    const int rows = in_sizes[0] / ROW_C;              // 16384
    tpq_kernel<<<rows / RPT, NT, smem_bytes>>>(x, inv, out);
}